// round 1
// baseline (speedup 1.0000x reference)
#include <cuda_runtime.h>

// Problem constants (fixed by the dataset)
#define NTOK 262144
#define NSEG 4096
#define DDIM 256
#define ADIM 128
#define NB   256      // scan blocks: NTOK / 1024

// ---------------- scratch (no allocations allowed) ----------------
__device__ int      d_seg[NTOK];
__device__ int      d_ends[NSEG];
__device__ int      d_bsums[NB];
__device__ float    d_Mt[DDIM * DDIM];     // Mt[k][n] = sum_a Wq[a][k] * Wk[a][n]
__device__ float    d_V[NSEG * DDIM];      // v_b = (Wk^T Wq) x_end_b
__device__ float    d_logits[NTOK];
__device__ unsigned d_smax[NSEG];          // order-encoded float max
__device__ float    d_denom[NSEG];

// order-preserving float<->uint encoding for atomicMax
__device__ __forceinline__ unsigned encf(float f) {
    unsigned u = __float_as_uint(f);
    return (u & 0x80000000u) ? ~u : (u | 0x80000000u);
}
__device__ __forceinline__ float decf(unsigned u) {
    return __uint_as_float((u & 0x80000000u) ? (u ^ 0x80000000u) : ~u);
}

// ---------------- init ----------------
__global__ void initK() {
    int i = blockIdx.x * 256 + threadIdx.x;
    if (i < NSEG) { d_smax[i] = 0u; d_denom[i] = 0.0f; }
}

// ---------------- 3-phase scan of `queries` -> seg ids + ends ----------------
__global__ void scanA(const int* __restrict__ q) {
    __shared__ int sm[256];
    int t = threadIdx.x;
    int4 v = ((const int4*)q)[blockIdx.x * 256 + t];
    sm[t] = v.x + v.y + v.z + v.w;
    __syncthreads();
    for (int off = 128; off > 0; off >>= 1) {
        if (t < off) sm[t] += sm[t + off];
        __syncthreads();
    }
    if (t == 0) d_bsums[blockIdx.x] = sm[0];
}

__global__ void scanB() {
    __shared__ int sm[NB];
    int t = threadIdx.x;
    int own = d_bsums[t];
    sm[t] = own;
    __syncthreads();
    for (int off = 1; off < NB; off <<= 1) {
        int x = (t >= off) ? sm[t - off] : 0;
        __syncthreads();
        sm[t] += x;
        __syncthreads();
    }
    d_bsums[t] = sm[t] - own;   // exclusive
}

__global__ void scanC(const int* __restrict__ q) {
    __shared__ int sm[256];
    int t = threadIdx.x;
    int4 v = ((const int4*)q)[blockIdx.x * 256 + t];
    int s = v.x + v.y + v.z + v.w;
    sm[t] = s;
    __syncthreads();
    for (int off = 1; off < 256; off <<= 1) {
        int x = (t >= off) ? sm[t - off] : 0;
        __syncthreads();
        sm[t] += x;
        __syncthreads();
    }
    int p = d_bsums[blockIdx.x] + sm[t] - s;   // exclusive prefix at this thread
    int i0 = (blockIdx.x * 256 + t) * 4;
    int4 sv;
    sv.x = p; if (v.x) { d_ends[p] = i0 + 0; p++; }
    sv.y = p; if (v.y) { d_ends[p] = i0 + 1; p++; }
    sv.z = p; if (v.z) { d_ends[p] = i0 + 2; p++; }
    sv.w = p; if (v.w) { d_ends[p] = i0 + 3; p++; }
    ((int4*)d_seg)[blockIdx.x * 256 + t] = sv;
}

// ---------------- Mt[k][n] = sum_a Wq[a][k] * Wk[a][n] ----------------
__global__ void mtK(const float* __restrict__ Wq, const float* __restrict__ Wk) {
    int k = blockIdx.x;     // 0..255
    int n = threadIdx.x;    // 0..255
    float acc = 0.0f;
#pragma unroll 8
    for (int a = 0; a < ADIM; a++)
        acc += __ldg(Wq + a * DDIM + k) * __ldg(Wk + a * DDIM + n);
    d_Mt[k * DDIM + n] = acc;
}

// ---------------- V = gather(X, ends) @ Mt  (4096x256 @ 256x256) ----------------
// BM=64, BN=64, BK=32, 256 threads, 4x4 register tile per thread.
__global__ void gemmV(const float* __restrict__ X) {
    __shared__ float As[64][33];                 // padded: conflict-free
    __shared__ __align__(16) float Bs[32][64];
    __shared__ int endsS[64];

    int t  = threadIdx.x;
    int rb = blockIdx.y;     // segment-tile: 0..63
    int nb = blockIdx.x;     // n-tile: 0..3
    if (t < 64) endsS[t] = d_ends[rb * 64 + t];
    __syncthreads();

    int tx = t & 15;         // n direction
    int ty = t >> 4;         // m direction
    float acc[4][4];
#pragma unroll
    for (int i = 0; i < 4; i++)
#pragma unroll
        for (int j = 0; j < 4; j++) acc[i][j] = 0.0f;

    for (int kt = 0; kt < 8; kt++) {
        // load A tile: 64 rows x 32 k (gathered), 512 float4 by 256 threads
#pragma unroll
        for (int l = 0; l < 2; l++) {
            int f   = t + l * 256;
            int row = f >> 3;
            int k4  = f & 7;
            float4 x = __ldg((const float4*)(X + (size_t)endsS[row] * DDIM + kt * 32) + k4);
            As[row][k4 * 4 + 0] = x.x;
            As[row][k4 * 4 + 1] = x.y;
            As[row][k4 * 4 + 2] = x.z;
            As[row][k4 * 4 + 3] = x.w;
        }
        // load B tile: 32 x 64
#pragma unroll
        for (int l = 0; l < 2; l++) {
            int f  = t + l * 256;
            int kk = f >> 4;
            int n4 = f & 15;
            float4 b = __ldg((const float4*)(d_Mt + (kt * 32 + kk) * DDIM + nb * 64) + n4);
            *(float4*)&Bs[kk][n4 * 4] = b;
        }
        __syncthreads();
#pragma unroll
        for (int kk = 0; kk < 32; kk++) {
            float a0 = As[ty * 4 + 0][kk];
            float a1 = As[ty * 4 + 1][kk];
            float a2 = As[ty * 4 + 2][kk];
            float a3 = As[ty * 4 + 3][kk];
            float4 b = *(const float4*)&Bs[kk][tx * 4];
            acc[0][0] += a0 * b.x; acc[0][1] += a0 * b.y; acc[0][2] += a0 * b.z; acc[0][3] += a0 * b.w;
            acc[1][0] += a1 * b.x; acc[1][1] += a1 * b.y; acc[1][2] += a1 * b.z; acc[1][3] += a1 * b.w;
            acc[2][0] += a2 * b.x; acc[2][1] += a2 * b.y; acc[2][2] += a2 * b.z; acc[2][3] += a2 * b.w;
            acc[3][0] += a3 * b.x; acc[3][1] += a3 * b.y; acc[3][2] += a3 * b.z; acc[3][3] += a3 * b.w;
        }
        __syncthreads();
    }
#pragma unroll
    for (int i = 0; i < 4; i++) {
        float4 o = make_float4(acc[i][0], acc[i][1], acc[i][2], acc[i][3]);
        *(float4*)(d_V + (size_t)(rb * 64 + ty * 4 + i) * DDIM + nb * 64 + tx * 4) = o;
    }
}

// ---------------- logits: warp per token, streaming X ----------------
__global__ void logitsK(const float* __restrict__ X) {
    int token = blockIdx.x * 8 + (threadIdx.x >> 5);
    int lane  = threadIdx.x & 31;
    int s = d_seg[token];
    const float4* xr = (const float4*)X + (size_t)token * 64;
    const float4* vr = (const float4*)d_V + (size_t)s * 64;

    float4 a = __ldcs(xr + lane);
    float4 b = __ldg(vr + lane);
    float p = a.x * b.x + a.y * b.y + a.z * b.z + a.w * b.w;
    a = __ldcs(xr + lane + 32);
    b = __ldg(vr + lane + 32);
    p += a.x * b.x + a.y * b.y + a.z * b.z + a.w * b.w;

#pragma unroll
    for (int off = 16; off > 0; off >>= 1)
        p += __shfl_down_sync(0xffffffffu, p, off);
    if (lane == 0) d_logits[token] = p;
}

// ---------------- segment max (warp-segmented; seg is non-decreasing) ----------------
__global__ void maxK() {
    int i    = blockIdx.x * 256 + threadIdx.x;
    int lane = threadIdx.x & 31;
    float l = d_logits[i];
    int   s = d_seg[i];
#pragma unroll
    for (int off = 1; off < 32; off <<= 1) {
        float lo = __shfl_down_sync(0xffffffffu, l, off);
        int   so = __shfl_down_sync(0xffffffffu, s, off);
        if (lane + off < 32 && so == s) l = fmaxf(l, lo);
    }
    int sprev = __shfl_up_sync(0xffffffffu, s, 1);
    if (lane == 0 || sprev != s)
        atomicMax(&d_smax[s], encf(l));
}

// ---------------- exp + segment sum ----------------
__global__ void expsumK(float* __restrict__ out) {
    int i    = blockIdx.x * 256 + threadIdx.x;
    int lane = threadIdx.x & 31;
    float l = d_logits[i];
    int   s = d_seg[i];
    float m = decf(d_smax[s]);
    float e = __expf(l - m);
    out[i] = e;
    float sum = e;
#pragma unroll
    for (int off = 1; off < 32; off <<= 1) {
        float so_sum = __shfl_down_sync(0xffffffffu, sum, off);
        int   so     = __shfl_down_sync(0xffffffffu, s, off);
        if (lane + off < 32 && so == s) sum += so_sum;
    }
    int sprev = __shfl_up_sync(0xffffffffu, s, 1);
    if (lane == 0 || sprev != s)
        atomicAdd(&d_denom[s], sum);
}

// ---------------- normalize ----------------
__global__ void divK(float* __restrict__ out) {
    int i = blockIdx.x * 256 + threadIdx.x;
    int s = d_seg[i];
    out[i] = out[i] / d_denom[s];
}

extern "C" void kernel_launch(void* const* d_in, const int* in_sizes, int n_in,
                              void* d_out, int out_size) {
    const float* X  = (const float*)d_in[0];
    const int*   q  = (const int*)d_in[1];
    const float* Wq = (const float*)d_in[3];
    const float* Wk = (const float*)d_in[4];
    float* out = (float*)d_out;

    initK<<<16, 256>>>();
    scanA<<<NB, 256>>>(q);
    scanB<<<1, NB>>>();
    scanC<<<NB, 256>>>(q);
    mtK<<<DDIM, DDIM>>>(Wq, Wk);
    gemmV<<<dim3(DDIM / 64, NSEG / 64), 256>>>(X);
    logitsK<<<NTOK / 8, 256>>>(X);
    maxK<<<NTOK / 256, 256>>>();
    expsumK<<<NTOK / 256, 256>>>(out);
    divK<<<NTOK / 256, 256>>>(out);
}